// round 12
// baseline (speedup 1.0000x reference)
#include <cuda_runtime.h>
#include <cstdint>
#include <cstring>

#define BB 16
#define NN 128
#define DD 128

#define PREP_BLOCKS 256

// Split-K GEMM config (R7-proven)
#define SK  8
#define KB  64
#define SBM 64
#define SBK 16

// Scratch (device globals — allocations forbidden)
__device__ float g_xfull[BB * NN * 512];     // [hhat | deg*h | ehat | h]
__device__ float g_G[512 * 128];
__device__ float g_bb[128];
__device__ float g_deg[BB * NN];
__device__ float g_part[SK * BB * NN * 128];

__device__ __forceinline__ unsigned long long f2ull(float x, float y) {
    float2 v = make_float2(x, y);
    unsigned long long u; memcpy(&u, &v, 8); return u;
}
__device__ __forceinline__ float2 ull2f(unsigned long long u) {
    float2 v; memcpy(&v, &u, 8); return v;
}

// ---------------------------------------------------------------------------
// Fused kernel: [0,256) prep ; [256, 2304) reduce with cp.async e-streaming.
// ---------------------------------------------------------------------------
__global__ void __launch_bounds__(256) fused_prep_reduce(
    const float* __restrict__ h,
    const float* __restrict__ adj,
    const float* __restrict__ e,
    const float* __restrict__ Wm,
    const float* __restrict__ Wu,
    const float* __restrict__ bm,
    float* __restrict__ xfull,
    float* __restrict__ deg_out,
    float* __restrict__ G,
    float* __restrict__ bb)
{
    const int tid  = threadIdx.x;
    const int lane = tid & 31;
    const int w    = tid >> 5;

    if (blockIdx.x < PREP_BLOCKS) {
        // ----------------------- prep path -----------------------
        __shared__ float s_wm[2][128];
        const int pid = blockIdx.x;
        const int c0  = pid * 2;
        const int cl  = tid >> 7;
        const int k   = tid & 127;

        {
            const int q  = tid & 127;
            const int cc = c0 + (tid >> 7);
            s_wm[tid >> 7][q] = (cc < 384) ? Wm[(size_t)q * 384 + cc] : 0.f;
        }
        __syncthreads();

        const int c = c0 + cl;
        if (c < 384) {
            const float* __restrict__ wu = Wu + (size_t)k * 256 + 128;
            float acc = 0.f;
            #pragma unroll 4
            for (int q = 0; q < 128; q += 4) {
                const float4 v = *(const float4*)(wu + q);
                acc += s_wm[cl][q]     * v.x;
                acc += s_wm[cl][q + 1] * v.y;
                acc += s_wm[cl][q + 2] * v.z;
                acc += s_wm[cl][q + 3] * v.w;
            }
            G[(size_t)c * 128 + k] = acc;
        } else {
            G[(size_t)c * 128 + k] = Wu[(size_t)k * 256 + (c - 384)];
        }

        if (pid == 0 && tid < 128) {
            const float* __restrict__ wu = Wu + (size_t)tid * 256 + 128;
            float acc = 0.f;
            #pragma unroll 4
            for (int q = 0; q < 128; q += 4) {
                const float4 v  = *(const float4*)(wu + q);
                const float4 bv = *(const float4*)(bm + q);
                acc += bv.x * v.x + bv.y * v.y + bv.z * v.z + bv.w * v.w;
            }
            bb[tid] = acc;
        }
        return;
    }

    // ----------------------- reduce path -----------------------
    const int rid = blockIdx.x - PREP_BLOCKS;
    const int j = rid & (NN - 1);
    const int b = rid >> 7;

    __shared__ __align__(16) float  s_ebuf[2][16][DD];  // 16 KB, 2-stage
    __shared__ __align__(16) float  s_re[8][DD];
    __shared__ __align__(16) float  s_rh[8][DD];
    __shared__ __align__(8)  float2 s_pair[144];        // 128 + 16 pad
    __shared__ unsigned s_ball[4];
    __shared__ float    s_wsum[4];

    float a = 0.f;
    if (tid < NN) {
        a = adj[((size_t)b * NN + tid) * NN + j];
        unsigned ball = __ballot_sync(0xffffffffu, a != 0.f);
        float s = a;
        #pragma unroll
        for (int off = 16; off; off >>= 1) s += __shfl_down_sync(0xffffffffu, s, off);
        if (lane == 0) { s_ball[w] = ball; s_wsum[w] = s; }
    }
    __syncthreads();

    const unsigned bl0 = s_ball[0], bl1 = s_ball[1], bl2 = s_ball[2], bl3 = s_ball[3];
    const int cnt = __popc(bl0) + __popc(bl1) + __popc(bl2) + __popc(bl3);
    const float deg = s_wsum[0] + s_wsum[1] + s_wsum[2] + s_wsum[3];

    if (tid < NN && a != 0.f) {
        int base = 0;
        if (w > 0) base += __popc(bl0);
        if (w > 1) base += __popc(bl1);
        if (w > 2) base += __popc(bl2);
        const unsigned ball = s_ball[w];
        const int pos = base + __popc(ball & ((1u << lane) - 1u));
        s_pair[pos] = make_float2(a, __int_as_float(tid));
    }
    if (tid < 16) s_pair[cnt + tid] = make_float2(0.f, __int_as_float(0));
    __syncthreads();

    const int nst = (cnt + 15) >> 4;   // stages of 16 rows

    // e row base for this (b,j): e[b,i,j,:] = ebase + i*NN*DD
    const float* __restrict__ ebase = e + ((size_t)b * NN * NN + (size_t)j) * DD;
    const float* __restrict__ hb    = h + (size_t)b * NN * DD + lane * 4;

    // smem u32 base of s_ebuf for cp.async
    const unsigned ebuf_sa = (unsigned)__cvta_generic_to_shared(&s_ebuf[0][0][0]);

    // issue one stage: 16 rows x 512B via 2 rounds of 256x16B cp.async.cg
    const int c_row = tid >> 5;        // 0..7 (+q*8)
    const int c_chk = (tid & 31) * 4;  // float offset of 16B chunk

    #define ISSUE_STAGE(S)                                                     \
    {                                                                          \
        const int _buf = (S) & 1;                                              \
        _Pragma("unroll")                                                      \
        for (int q = 0; q < 2; ++q) {                                          \
            const int row = q * 8 + c_row;                                     \
            const float2 pr = s_pair[(S) * 16 + row];                          \
            const int i = __float_as_int(pr.y);                                \
            const float* src = ebase + (size_t)i * (NN * DD) + c_chk;          \
            const unsigned dst = ebuf_sa + ((_buf * 16 + row) * DD + c_chk) * 4;\
            asm volatile("cp.async.cg.shared.global [%0], [%1], 16;"           \
                         :: "r"(dst), "l"(src));                               \
        }                                                                      \
    }

    if (nst > 0) ISSUE_STAGE(0);
    asm volatile("cp.async.commit_group;");
    if (nst > 1) ISSUE_STAGE(1);
    asm volatile("cp.async.commit_group;");

    float4 ae = make_float4(0.f, 0.f, 0.f, 0.f);
    float4 ah = make_float4(0.f, 0.f, 0.f, 0.f);

    for (int s = 0; s < nst; ++s) {
        asm volatile("cp.async.wait_group 1;");
        __syncthreads();

        const int buf = s & 1;
        #pragma unroll
        for (int k = 0; k < 2; ++k) {
            const int rr = w * 2 + k;                 // 0..15 within stage
            const float2 pr = s_pair[s * 16 + rr];
            const float aa = pr.x;
            const int   i  = __float_as_int(pr.y);
            const float4 hv = *(const float4*)(hb + (size_t)i * DD);
            const float4 ev = *(const float4*)&s_ebuf[buf][rr][lane * 4];
            ae.x += aa * ev.x; ae.y += aa * ev.y; ae.z += aa * ev.z; ae.w += aa * ev.w;
            ah.x += aa * hv.x; ah.y += aa * hv.y; ah.z += aa * hv.z; ah.w += aa * hv.w;
        }
        __syncthreads();   // all warps done reading buf before re-fill

        if (s + 2 < nst) ISSUE_STAGE(s + 2);
        asm volatile("cp.async.commit_group;");
    }
    #undef ISSUE_STAGE

    *(float4*)&s_re[w][lane * 4] = ae;
    *(float4*)&s_rh[w][lane * 4] = ah;
    __syncthreads();

    if (tid < NN) {
        float se = 0.f, sh = 0.f;
        #pragma unroll
        for (int ww = 0; ww < 8; ++ww) { se += s_re[ww][tid]; sh += s_rh[ww][tid]; }
        const size_t r  = (size_t)b * NN + j;
        const float  hv = h[r * DD + tid];
        xfull[r * 512 + tid]       = sh;        // hhat
        xfull[r * 512 + 128 + tid] = deg * hv;  // deg*h
        xfull[r * 512 + 256 + tid] = se;        // ehat
        xfull[r * 512 + 384 + tid] = hv;        // h
        if (tid == 0) deg_out[r] = deg;
    }
}

// ---------------------------------------------------------------------------
// Split-K GEMM (R7-proven, verbatim): part[ks] = A[:,ks*64:+64] @ G[ks*64:+64,:]
// ---------------------------------------------------------------------------
__global__ void __launch_bounds__(256) gemm_split(
    const float* __restrict__ A,
    const float* __restrict__ G,
    float* __restrict__ part)
{
    __shared__ __align__(16) float As[SBK][76];
    __shared__ __align__(16) float Bs[SBK][128];

    const int ks  = blockIdx.x;
    const int m0  = blockIdx.y * SBM;
    const int kb  = ks * KB;
    const int tid = threadIdx.x;
    const int tx  = tid & 15;
    const int ty  = tid >> 4;

    const int am = tid >> 2;
    const int ak = (tid & 3) * 4;
    const int bk = tid >> 4;
    const int bc = (tid & 15) * 8;

    unsigned long long acc[4][4];
    #pragma unroll
    for (int i = 0; i < 4; ++i)
        #pragma unroll
        for (int jj = 0; jj < 4; ++jj) acc[i][jj] = 0ull;

    for (int t = 0; t < KB; t += SBK) {
        const float4 av = *(const float4*)(A + (size_t)(m0 + am) * 512 + kb + t + ak);
        As[ak + 0][am] = av.x; As[ak + 1][am] = av.y;
        As[ak + 2][am] = av.z; As[ak + 3][am] = av.w;
        const float* gr = G + (size_t)(kb + t + bk) * 128 + bc;
        *(float4*)&Bs[bk][bc]     = *(const float4*)(gr);
        *(float4*)&Bs[bk][bc + 4] = *(const float4*)(gr + 4);
        __syncthreads();

        #pragma unroll
        for (int kk = 0; kk < SBK; ++kk) {
            const float4 a  = *(const float4*)&As[kk][ty * 4];
            const float4 b0 = *(const float4*)&Bs[kk][tx * 8];
            const float4 b1 = *(const float4*)&Bs[kk][tx * 8 + 4];
            unsigned long long aa[4], bbv[4];
            aa[0] = f2ull(a.x, a.x); aa[1] = f2ull(a.y, a.y);
            aa[2] = f2ull(a.z, a.z); aa[3] = f2ull(a.w, a.w);
            bbv[0] = f2ull(b0.x, b0.y); bbv[1] = f2ull(b0.z, b0.w);
            bbv[2] = f2ull(b1.x, b1.y); bbv[3] = f2ull(b1.z, b1.w);
            #pragma unroll
            for (int i = 0; i < 4; ++i)
                #pragma unroll
                for (int jj = 0; jj < 4; ++jj)
                    asm("fma.rn.f32x2 %0, %1, %2, %0;"
                        : "+l"(acc[i][jj]) : "l"(aa[i]), "l"(bbv[jj]));
        }
        __syncthreads();
    }

    float* p = part + (size_t)ks * (BB * NN * 128);
    #pragma unroll
    for (int i = 0; i < 4; ++i) {
        const int row = m0 + ty * 4 + i;
        const float2 v0 = ull2f(acc[i][0]);
        const float2 v1 = ull2f(acc[i][1]);
        const float2 v2 = ull2f(acc[i][2]);
        const float2 v3 = ull2f(acc[i][3]);
        float4 o0 = make_float4(v0.x, v0.y, v1.x, v1.y);
        float4 o1 = make_float4(v2.x, v2.y, v3.x, v3.y);
        *(float4*)(p + (size_t)row * 128 + tx * 8)     = o0;
        *(float4*)(p + (size_t)row * 128 + tx * 8 + 4) = o1;
    }
}

// ---------------------------------------------------------------------------
// finish: C = sum_ks part[ks] + deg⊗bb + bu   (part is L2-resident)
// ---------------------------------------------------------------------------
__global__ void __launch_bounds__(128) finish_kernel(
    const float* __restrict__ part,
    const float* __restrict__ bb,
    const float* __restrict__ bu,
    const float* __restrict__ deg,
    float* __restrict__ C)
{
    const int t   = blockIdx.x * 128 + threadIdx.x;
    const int row = t >> 5;
    const int c4  = (t & 31) * 4;
    const size_t off = (size_t)row * 128 + c4;

    float4 s = make_float4(0.f, 0.f, 0.f, 0.f);
    #pragma unroll
    for (int ks = 0; ks < SK; ++ks) {
        const float4 v = *(const float4*)(part + (size_t)ks * (BB * NN * 128) + off);
        s.x += v.x; s.y += v.y; s.z += v.z; s.w += v.w;
    }
    const float dg = __ldg(deg + row);
    const float4 bbv = *(const float4*)(bb + c4);
    const float4 buv = *(const float4*)(bu + c4);
    s.x += dg * bbv.x + buv.x;
    s.y += dg * bbv.y + buv.y;
    s.z += dg * bbv.z + buv.z;
    s.w += dg * bbv.w + buv.w;
    *(float4*)(C + off) = s;
}

// ---------------------------------------------------------------------------
// kernel_launch: inputs: h, adj, e, Wm, bm, Wu, bu ; output (B,N,D) fp32
// ---------------------------------------------------------------------------
extern "C" void kernel_launch(void* const* d_in, const int* in_sizes, int n_in,
                              void* d_out, int out_size)
{
    const float* h   = (const float*)d_in[0];
    const float* adj = (const float*)d_in[1];
    const float* e   = (const float*)d_in[2];
    const float* Wm  = (const float*)d_in[3];
    const float* bm  = (const float*)d_in[4];
    const float* Wu  = (const float*)d_in[5];
    const float* bu  = (const float*)d_in[6];
    float* out = (float*)d_out;

    float* xfull; cudaGetSymbolAddress((void**)&xfull, g_xfull);
    float* G;     cudaGetSymbolAddress((void**)&G,     g_G);
    float* bb;    cudaGetSymbolAddress((void**)&bb,    g_bb);
    float* deg;   cudaGetSymbolAddress((void**)&deg,   g_deg);
    float* part;  cudaGetSymbolAddress((void**)&part,  g_part);

    fused_prep_reduce<<<PREP_BLOCKS + BB * NN, 256>>>(
        h, adj, e, Wm, Wu, bm, xfull, deg, G, bb);

    {
        dim3 grid(SK, (BB * NN) / SBM);   // (8, 32)
        gemm_split<<<grid, 256>>>(xfull, G, part);
    }
    finish_kernel<<<512, 128>>>(part, bb, bu, deg, out);
}

// round 13
// speedup vs baseline: 1.2059x; 1.2059x over previous
#include <cuda_runtime.h>
#include <cstdint>
#include <cstring>

#define BB 16
#define NN 128
#define DD 128

#define PREP_BLOCKS 256

// Split-K GEMM config
#define SK  8
#define KB  64
#define SBM 64
#define SBK 16

// Scratch (device globals — allocations forbidden)
__device__ float g_xfull[BB * NN * 512];     // [hhat | deg*h | ehat | h]
__device__ float g_G[512 * 128];
__device__ float g_bb[128];
__device__ float g_deg[BB * NN];
__device__ float g_part[SK * BB * NN * 128];

__device__ __forceinline__ unsigned long long f2ull(float x, float y) {
    float2 v = make_float2(x, y);
    unsigned long long u; memcpy(&u, &v, 8); return u;
}
__device__ __forceinline__ float2 ull2f(unsigned long long u) {
    float2 v; memcpy(&v, &u, 8); return v;
}

// ---------------------------------------------------------------------------
// Fused kernel — R7-verbatim reduce (measured 25.4us, regs 32, occ 87%).
// [0,256) prep ; [256, 2304) e+h reduce.
// ---------------------------------------------------------------------------
__global__ void __launch_bounds__(256) fused_prep_reduce(
    const float* __restrict__ h,
    const float* __restrict__ adj,
    const float* __restrict__ e,
    const float* __restrict__ Wm,
    const float* __restrict__ Wu,
    const float* __restrict__ bm,
    float* __restrict__ xfull,
    float* __restrict__ deg_out,
    float* __restrict__ G,
    float* __restrict__ bb)
{
    const int tid  = threadIdx.x;
    const int lane = tid & 31;
    const int w    = tid >> 5;

    if (blockIdx.x < PREP_BLOCKS) {
        // ----------------------- prep path -----------------------
        __shared__ float s_wm[2][128];
        const int pid = blockIdx.x;
        const int c0  = pid * 2;
        const int cl  = tid >> 7;
        const int k   = tid & 127;

        {
            const int q  = tid & 127;
            const int cc = c0 + (tid >> 7);
            s_wm[tid >> 7][q] = (cc < 384) ? Wm[(size_t)q * 384 + cc] : 0.f;
        }
        __syncthreads();

        const int c = c0 + cl;
        if (c < 384) {
            const float* __restrict__ wu = Wu + (size_t)k * 256 + 128;
            float acc = 0.f;
            #pragma unroll 4
            for (int q = 0; q < 128; q += 4) {
                const float4 v = *(const float4*)(wu + q);
                acc += s_wm[cl][q]     * v.x;
                acc += s_wm[cl][q + 1] * v.y;
                acc += s_wm[cl][q + 2] * v.z;
                acc += s_wm[cl][q + 3] * v.w;
            }
            G[(size_t)c * 128 + k] = acc;
        } else {
            G[(size_t)c * 128 + k] = Wu[(size_t)k * 256 + (c - 384)];
        }

        if (pid == 0 && tid < 128) {
            const float* __restrict__ wu = Wu + (size_t)tid * 256 + 128;
            float acc = 0.f;
            #pragma unroll 4
            for (int q = 0; q < 128; q += 4) {
                const float4 v  = *(const float4*)(wu + q);
                const float4 bv = *(const float4*)(bm + q);
                acc += bv.x * v.x + bv.y * v.y + bv.z * v.z + bv.w * v.w;
            }
            bb[tid] = acc;
        }
        return;
    }

    // ----------------------- reduce path (R7-verbatim) -----------------------
    const int rid = blockIdx.x - PREP_BLOCKS;
    const int j = rid & (NN - 1);
    const int b = rid >> 7;

    __shared__ __align__(16) float s_re[8][DD];
    __shared__ __align__(16) float s_rh[8][DD];
    __shared__ float    s_val[NN];
    __shared__ int      s_idx[NN];
    __shared__ unsigned s_ball[4];
    __shared__ float    s_wsum[4];
    __shared__ int      s_cnt;
    __shared__ float    s_deg;

    float a = 0.f;
    if (tid < NN) {
        a = adj[((size_t)b * NN + tid) * NN + j];
        unsigned ball = __ballot_sync(0xffffffffu, a != 0.f);
        float s = a;
        #pragma unroll
        for (int off = 16; off; off >>= 1) s += __shfl_down_sync(0xffffffffu, s, off);
        if (lane == 0) { s_ball[w] = ball; s_wsum[w] = s; }
    }
    __syncthreads();
    if (tid < NN) {
        int base = 0;
        #pragma unroll
        for (int ww = 0; ww < 4; ++ww) if (ww < w) base += __popc(s_ball[ww]);
        const unsigned ball = s_ball[w];
        if (a != 0.f) {
            const int pos = base + __popc(ball & ((1u << lane) - 1u));
            s_idx[pos] = tid;
            s_val[pos] = a;
        }
        if (tid == 0) {
            s_cnt = __popc(s_ball[0]) + __popc(s_ball[1]) + __popc(s_ball[2]) + __popc(s_ball[3]);
            s_deg = s_wsum[0] + s_wsum[1] + s_wsum[2] + s_wsum[3];
        }
    }
    __syncthreads();

    const int cnt = s_cnt;
    const float deg = s_deg;

    // e[b,i,j,d]: base (i=0) = (b*NN*NN + j)*DD ; stride over i = NN*DD
    const float* __restrict__ eb = e + ((size_t)b * NN * NN + (size_t)j) * DD + lane * 4;
    const float* __restrict__ hb = h + (size_t)b * NN * DD + lane * 4;

    float4 ae = make_float4(0.f, 0.f, 0.f, 0.f);
    float4 ah = make_float4(0.f, 0.f, 0.f, 0.f);
    #pragma unroll 4
    for (int t = w; t < cnt; t += 8) {
        const float aa = s_val[t];
        const int   i  = s_idx[t];
        const float4 ev = *(const float4*)(eb + (size_t)i * (NN * DD));
        const float4 hv = *(const float4*)(hb + (size_t)i * DD);
        ae.x += aa * ev.x; ae.y += aa * ev.y; ae.z += aa * ev.z; ae.w += aa * ev.w;
        ah.x += aa * hv.x; ah.y += aa * hv.y; ah.z += aa * hv.z; ah.w += aa * hv.w;
    }
    *(float4*)&s_re[w][lane * 4] = ae;
    *(float4*)&s_rh[w][lane * 4] = ah;
    __syncthreads();

    if (tid < NN) {
        float se = 0.f, sh = 0.f;
        #pragma unroll
        for (int ww = 0; ww < 8; ++ww) { se += s_re[ww][tid]; sh += s_rh[ww][tid]; }
        const size_t r  = (size_t)b * NN + j;
        const float  hv = h[r * DD + tid];
        xfull[r * 512 + tid]       = sh;        // hhat
        xfull[r * 512 + 128 + tid] = deg * hv;  // deg*h
        xfull[r * 512 + 256 + tid] = se;        // ehat
        xfull[r * 512 + 384 + tid] = hv;        // h
        if (tid == 0) deg_out[r] = deg;
    }
}

// ---------------------------------------------------------------------------
// Split-K GEMM, rebalanced: 128 threads, tile 64x128, TM=8 x TN=8.
// Per kk: 32B A + 32B B per thread for 64 MACs = 1.0 B/MAC (smem == FMA floor).
// Grid (8, 32) = 256 blocks.
// ---------------------------------------------------------------------------
__global__ void __launch_bounds__(128) gemm_split(
    const float* __restrict__ A,     // 2048 x 512
    const float* __restrict__ G,     // 512 x 128
    float* __restrict__ part)        // SK x 2048 x 128
{
    __shared__ __align__(16) float As[SBK][68];   // 272B row stride (16B mult)
    __shared__ __align__(16) float Bs[SBK][128];

    const int ks  = blockIdx.x;
    const int m0  = blockIdx.y * SBM;
    const int kb  = ks * KB;
    const int tid = threadIdx.x;
    const int tx  = tid & 15;     // 16 n-groups x 8 cols
    const int ty  = tid >> 4;     // 8  m-groups x 8 rows

    const int am = tid >> 1;          // 0..63
    const int ak = (tid & 1) * 8;     // 0, 8
    const int bk = tid >> 3;          // 0..15
    const int bc = (tid & 7) * 16;    // 0..112

    unsigned long long acc[8][4];
    #pragma unroll
    for (int i = 0; i < 8; ++i)
        #pragma unroll
        for (int jj = 0; jj < 4; ++jj) acc[i][jj] = 0ull;

    for (int t = 0; t < KB; t += SBK) {
        // A tile: 64 x 16, each thread 8 floats (2 float4), stored transposed
        {
            const float* ar = A + (size_t)(m0 + am) * 512 + kb + t + ak;
            const float4 a0 = *(const float4*)(ar);
            const float4 a1 = *(const float4*)(ar + 4);
            As[ak + 0][am] = a0.x; As[ak + 1][am] = a0.y;
            As[ak + 2][am] = a0.z; As[ak + 3][am] = a0.w;
            As[ak + 4][am] = a1.x; As[ak + 5][am] = a1.y;
            As[ak + 6][am] = a1.z; As[ak + 7][am] = a1.w;
        }
        // B tile: 16 x 128, each thread 16 floats (4 float4)
        {
            const float* gr = G + (size_t)(kb + t + bk) * 128 + bc;
            *(float4*)&Bs[bk][bc]      = *(const float4*)(gr);
            *(float4*)&Bs[bk][bc + 4]  = *(const float4*)(gr + 4);
            *(float4*)&Bs[bk][bc + 8]  = *(const float4*)(gr + 8);
            *(float4*)&Bs[bk][bc + 12] = *(const float4*)(gr + 12);
        }
        __syncthreads();

        #pragma unroll
        for (int kk = 0; kk < SBK; ++kk) {
            const float4 pa0 = *(const float4*)&As[kk][ty * 8];
            const float4 pa1 = *(const float4*)&As[kk][ty * 8 + 4];
            const float4 pb0 = *(const float4*)&Bs[kk][tx * 8];
            const float4 pb1 = *(const float4*)&Bs[kk][tx * 8 + 4];
            unsigned long long amv[8], bnv[4];
            amv[0] = f2ull(pa0.x, pa0.x); amv[1] = f2ull(pa0.y, pa0.y);
            amv[2] = f2ull(pa0.z, pa0.z); amv[3] = f2ull(pa0.w, pa0.w);
            amv[4] = f2ull(pa1.x, pa1.x); amv[5] = f2ull(pa1.y, pa1.y);
            amv[6] = f2ull(pa1.z, pa1.z); amv[7] = f2ull(pa1.w, pa1.w);
            bnv[0] = f2ull(pb0.x, pb0.y); bnv[1] = f2ull(pb0.z, pb0.w);
            bnv[2] = f2ull(pb1.x, pb1.y); bnv[3] = f2ull(pb1.z, pb1.w);
            #pragma unroll
            for (int i = 0; i < 8; ++i)
                #pragma unroll
                for (int jj = 0; jj < 4; ++jj)
                    asm("fma.rn.f32x2 %0, %1, %2, %0;"
                        : "+l"(acc[i][jj]) : "l"(amv[i]), "l"(bnv[jj]));
        }
        __syncthreads();
    }

    float* p = part + (size_t)ks * (BB * NN * 128);
    #pragma unroll
    for (int i = 0; i < 8; ++i) {
        const int row = m0 + ty * 8 + i;
        const float2 v0 = ull2f(acc[i][0]);
        const float2 v1 = ull2f(acc[i][1]);
        const float2 v2 = ull2f(acc[i][2]);
        const float2 v3 = ull2f(acc[i][3]);
        *(float4*)(p + (size_t)row * 128 + tx * 8)     = make_float4(v0.x, v0.y, v1.x, v1.y);
        *(float4*)(p + (size_t)row * 128 + tx * 8 + 4) = make_float4(v2.x, v2.y, v3.x, v3.y);
    }
}

// ---------------------------------------------------------------------------
// finish: C = sum_ks part[ks] + deg⊗bb + bu   (part is L2-resident)
// ---------------------------------------------------------------------------
__global__ void __launch_bounds__(128) finish_kernel(
    const float* __restrict__ part,
    const float* __restrict__ bb,
    const float* __restrict__ bu,
    const float* __restrict__ deg,
    float* __restrict__ C)
{
    const int t   = blockIdx.x * 128 + threadIdx.x;
    const int row = t >> 5;
    const int c4  = (t & 31) * 4;
    const size_t off = (size_t)row * 128 + c4;

    float4 s = make_float4(0.f, 0.f, 0.f, 0.f);
    #pragma unroll
    for (int ks = 0; ks < SK; ++ks) {
        const float4 v = *(const float4*)(part + (size_t)ks * (BB * NN * 128) + off);
        s.x += v.x; s.y += v.y; s.z += v.z; s.w += v.w;
    }
    const float dg = __ldg(deg + row);
    const float4 bbv = *(const float4*)(bb + c4);
    const float4 buv = *(const float4*)(bu + c4);
    s.x += dg * bbv.x + buv.x;
    s.y += dg * bbv.y + buv.y;
    s.z += dg * bbv.z + buv.z;
    s.w += dg * bbv.w + buv.w;
    *(float4*)(C + off) = s;
}

// ---------------------------------------------------------------------------
// kernel_launch: inputs: h, adj, e, Wm, bm, Wu, bu ; output (B,N,D) fp32
// ---------------------------------------------------------------------------
extern "C" void kernel_launch(void* const* d_in, const int* in_sizes, int n_in,
                              void* d_out, int out_size)
{
    const float* h   = (const float*)d_in[0];
    const float* adj = (const float*)d_in[1];
    const float* e   = (const float*)d_in[2];
    const float* Wm  = (const float*)d_in[3];
    const float* bm  = (const float*)d_in[4];
    const float* Wu  = (const float*)d_in[5];
    const float* bu  = (const float*)d_in[6];
    float* out = (float*)d_out;

    float* xfull; cudaGetSymbolAddress((void**)&xfull, g_xfull);
    float* G;     cudaGetSymbolAddress((void**)&G,     g_G);
    float* bb;    cudaGetSymbolAddress((void**)&bb,    g_bb);
    float* deg;   cudaGetSymbolAddress((void**)&deg,   g_deg);
    float* part;  cudaGetSymbolAddress((void**)&part,  g_part);

    fused_prep_reduce<<<PREP_BLOCKS + BB * NN, 256>>>(
        h, adj, e, Wm, Wu, bm, xfull, deg, G, bb);

    {
        dim3 grid(SK, (BB * NN) / SBM);   // (8, 32)
        gemm_split<<<grid, 256 / 2>>>(xfull, G, part);
    }
    finish_kernel<<<512, 128>>>(part, bb, bu, deg, out);
}